// round 1
// baseline (speedup 1.0000x reference)
#include <cuda_runtime.h>
#include <math.h>

#define Bb 1024
#define Lh 320
#define Dh 128
#define Eh 8
#define Kh 2
#define Ph 96
#define LK 32

// ---------------- scratch (device globals; no allocs allowed) ----------------
__device__ float g_buf[Bb * Lh];        // (B, L)
__device__ float gate_val[Bb * Kh];     // top-2 gate weights per row
__device__ int   gate_idx[Bb * Kh];     // top-2 expert ids per row
__device__ float imp_buf[Eh];           // importance = gates.sum(0)
__device__ float load_buf[Eh];          // load = prob.sum(0)

// ---------------- kernel 0: zero the accumulators (every launch) -------------
__global__ void zero_kernel() {
    int t = threadIdx.x;
    if (t < Eh) { imp_buf[t] = 0.f; load_buf[t] = 0.f; }
}

// ---------------- kernel 1: g[b,l] = x[b,l,:]·start_w + start_b --------------
// one warp per (b,l) row; 128 floats = exactly one float4 per lane
__global__ void g_kernel(const float* __restrict__ x,
                         const float* __restrict__ start_w,
                         const float* __restrict__ start_b) {
    int warp = (blockIdx.x * blockDim.x + threadIdx.x) >> 5;
    int lane = threadIdx.x & 31;
    if (warp >= Bb * Lh) return;
    float4 xv = ((const float4*)(x + (size_t)warp * Dh))[lane];
    float4 wv = ((const float4*)start_w)[lane];
    float s = xv.x * wv.x + xv.y * wv.y + xv.z * wv.z + xv.w * wv.w;
#pragma unroll
    for (int o = 16; o; o >>= 1) s += __shfl_xor_sync(0xffffffffu, s, o);
    if (lane == 0) g_buf[warp] = s + start_b[0];
}

// ---------------- kernel 2: gating per batch row ------------------------------
// block = 256 threads = 8 warps; warp e computes clean/noise dots for expert e
__device__ __forceinline__ float cdf_f(float v) {
    return 0.5f * (1.f + erff(v * 0.7071067811865475f));
}

__global__ void gate_kernel(const float* __restrict__ w_gate,
                            const float* __restrict__ w_noise,
                            const float* __restrict__ noise) {
    int b = blockIdx.x;
    int wid = threadIdx.x >> 5, lane = threadIdx.x & 31;
    __shared__ float sc[Eh], sn[Eh];
    const float* grow = g_buf + (size_t)b * Lh;
    float c = 0.f, nn = 0.f;
    for (int l = lane; l < Lh; l += 32) {
        float gv = grow[l];
        c  += gv * w_gate [l * Eh + wid];
        nn += gv * w_noise[l * Eh + wid];
    }
#pragma unroll
    for (int o = 16; o; o >>= 1) {
        c  += __shfl_xor_sync(0xffffffffu, c,  o);
        nn += __shfl_xor_sync(0xffffffffu, nn, o);
    }
    if (lane == 0) { sc[wid] = c; sn[wid] = nn; }
    __syncthreads();
    if (threadIdx.x == 0) {
        float clean[Eh], std_[Eh], noisy[Eh];
#pragma unroll
        for (int e = 0; e < Eh; e++) {
            clean[e] = sc[e];
            float v = sn[e];
            // stable softplus: log1p(exp(v))
            float sp = fmaxf(v, 0.f) + log1pf(expf(-fabsf(v)));
            std_[e] = sp + 0.01f;
            noisy[e] = clean[e] + noise[b * Eh + e] * std_[e];
        }
        // top-3 selection over 8
        int   idx[3];
        float val[3];
        bool used[Eh];
#pragma unroll
        for (int e = 0; e < Eh; e++) used[e] = false;
        for (int k = 0; k < 3; k++) {
            int bi = -1; float bv = -3.4e38f;
            for (int e = 0; e < Eh; e++)
                if (!used[e] && noisy[e] > bv) { bv = noisy[e]; bi = e; }
            used[bi] = true; idx[k] = bi; val[k] = bv;
        }
        // softmax over top-2
        float e1 = expf(val[1] - val[0]);
        float den = 1.f + e1;
        float g0 = 1.f / den, g1 = e1 / den;
        gate_val[b * 2]     = g0;  gate_val[b * 2 + 1] = g1;
        gate_idx[b * 2]     = idx[0]; gate_idx[b * 2 + 1] = idx[1];
        atomicAdd(&imp_buf[idx[0]], g0);
        atomicAdd(&imp_buf[idx[1]], g1);
        float thr_in = val[2], thr_out = val[1];
#pragma unroll
        for (int e = 0; e < Eh; e++) {
            float cc = isnan(clean[e]) ? 0.f : clean[e];
            float t  = (noisy[e] > thr_in) ? thr_in : thr_out;
            float prob = cdf_f((cc - t) / std_[e]);
            atomicAdd(&load_buf[e], prob);
        }
    }
}

// ---------------- kernel 3: balance loss --------------------------------------
__global__ void balance_kernel(float* __restrict__ out, int off) {
    if (threadIdx.x == 0) {
        float mi = 0.f, ml = 0.f;
        for (int e = 0; e < Eh; e++) { mi += imp_buf[e]; ml += load_buf[e]; }
        mi /= Eh; ml /= Eh;
        float vi = 0.f, vl = 0.f;
        for (int e = 0; e < Eh; e++) {
            float a = imp_buf[e] - mi;  vi += a * a;
            float c = load_buf[e] - ml; vl += c * c;
        }
        vi /= (Eh - 1); vl /= (Eh - 1);
        out[off]     = 0.01f * (vi / (mi * mi + 1e-10f) + vl / (ml * ml + 1e-10f));
        out[off + 1] = 0.f;  // regu_sum
    }
}

// ---------------- kernel 4: main batched GEMM ---------------------------------
// One CTA per b. out[b] (96x128) = W_b^T (96xL) @ x[b] (Lx128) + gate-weighted bias.
// W_b[l,p] = g0*expert_w[e0,l,p] + g1*expert_w[e1,l,p], built per 32-row chunk.
// 384 threads: pt=tid>>4 (0..23, 4 p's each), dt=tid&15 (0..15, 8 d's each).
// Accumulators are packed f32x2 pairs driven by PTX fma.rn.f32x2 (2 FMA/instr,
// ptxas never emits it from C++; doubles FFMA lane throughput on sm_103a).
__global__ __launch_bounds__(384) void moe_gemm_kernel(
    const float* __restrict__ x,
    const float* __restrict__ expert_w,
    const float* __restrict__ expert_b,
    float* __restrict__ out)
{
    __shared__ float xs[LK * Dh];   // 16 KB
    __shared__ float ws[LK * Ph];   // 12 KB
    int b   = blockIdx.x;
    int tid = threadIdx.x;
    int dt  = tid & 15;
    int pt  = tid >> 4;

    float g0 = gate_val[b * 2],  g1 = gate_val[b * 2 + 1];
    int   e0 = gate_idx[b * 2],  e1 = gate_idx[b * 2 + 1];

    const float* xg = x + (size_t)b * Lh * Dh;
    const float* w0 = expert_w + (size_t)e0 * Lh * Ph;
    const float* w1 = expert_w + (size_t)e1 * Lh * Ph;

    unsigned long long acc[4][4];
#pragma unroll
    for (int i = 0; i < 4; i++)
#pragma unroll
        for (int j = 0; j < 4; j++) acc[i][j] = 0ull;

    int wp_p    = tid % Ph;   // p column this thread fills in ws
    int wl_base = tid / Ph;   // 0..3

    for (int kc = 0; kc < Lh / LK; kc++) {
        // stage x chunk (32x128) as float4
        const float4* xg4 = (const float4*)(xg + kc * LK * Dh);
        float4* xs4 = (float4*)xs;
#pragma unroll
        for (int i = tid; i < LK * Dh / 4; i += 384) xs4[i] = xg4[i];
        // stage combined weight chunk (32x96)
#pragma unroll
        for (int it = 0; it < 8; it++) {
            int l = wl_base + it * 4;
            int gi = (kc * LK + l) * Ph + wp_p;
            ws[l * Ph + wp_p] = g0 * w0[gi] + g1 * w1[gi];
        }
        __syncthreads();

#pragma unroll 8
        for (int lk = 0; lk < LK; lk++) {
            float4 wv = *(const float4*)&ws[lk * Ph + pt * 4];
            unsigned long long wp[4];
            asm("mov.b64 %0,{%1,%1};" : "=l"(wp[0]) : "f"(wv.x));
            asm("mov.b64 %0,{%1,%1};" : "=l"(wp[1]) : "f"(wv.y));
            asm("mov.b64 %0,{%1,%1};" : "=l"(wp[2]) : "f"(wv.z));
            asm("mov.b64 %0,{%1,%1};" : "=l"(wp[3]) : "f"(wv.w));
            ulonglong2 xa = *(const ulonglong2*)&xs[lk * Dh + dt * 8];
            ulonglong2 xb = *(const ulonglong2*)&xs[lk * Dh + dt * 8 + 4];
            unsigned long long xp[4] = {xa.x, xa.y, xb.x, xb.y};
#pragma unroll
            for (int i = 0; i < 4; i++)
#pragma unroll
                for (int j = 0; j < 4; j++)
                    asm("fma.rn.f32x2 %0,%1,%2,%0;"
                        : "+l"(acc[i][j]) : "l"(wp[i]), "l"(xp[j]));
        }
        __syncthreads();
    }

    // epilogue: + g0*expert_b[e0] + g1*expert_b[e1], write out
    const float* b0 = expert_b + (size_t)e0 * Ph * Dh;
    const float* b1 = expert_b + (size_t)e1 * Ph * Dh;
    float* ob = out + (size_t)b * Ph * Dh;
#pragma unroll
    for (int i = 0; i < 4; i++) {
        int p = pt * 4 + i;
#pragma unroll
        for (int j = 0; j < 4; j++) {
            float lo, hi;
            asm("mov.b64 {%0,%1},%2;" : "=f"(lo), "=f"(hi) : "l"(acc[i][j]));
            int d = dt * 8 + j * 2;
            int off = p * Dh + d;
            ob[off]     = lo + g0 * b0[off]     + g1 * b1[off];
            ob[off + 1] = hi + g0 * b0[off + 1] + g1 * b1[off + 1];
        }
    }
}

// ---------------- launch -------------------------------------------------------
extern "C" void kernel_launch(void* const* d_in, const int* in_sizes, int n_in,
                              void* d_out, int out_size) {
    // dict order: x, x_mark_enc, noise, start_w, start_b, w_gate, w_noise, expert_w, expert_b
    const float* x        = (const float*)d_in[0];
    const float* noise    = (const float*)d_in[2];
    const float* start_w  = (const float*)d_in[3];
    const float* start_b  = (const float*)d_in[4];
    const float* w_gate   = (const float*)d_in[5];
    const float* w_noise  = (const float*)d_in[6];
    const float* expert_w = (const float*)d_in[7];
    const float* expert_b = (const float*)d_in[8];
    // resolve expert_w/expert_b order by element count (245760 vs 98304)
    if (in_sizes[7] == Eh * Ph * Dh && in_sizes[8] == Eh * Lh * Ph) {
        expert_b = (const float*)d_in[7];
        expert_w = (const float*)d_in[8];
    }
    float* out = (float*)d_out;

    zero_kernel<<<1, 32>>>();
    g_kernel<<<(Bb * Lh) / 8, 256>>>(x, start_w, start_b);
    gate_kernel<<<Bb, 256>>>(w_gate, w_noise, noise);
    balance_kernel<<<1, 32>>>(out, out_size - 2);
    moe_gemm_kernel<<<Bb, 384>>>(x, expert_w, expert_b, out);
}

// round 2
// speedup vs baseline: 1.2430x; 1.2430x over previous
#include <cuda_runtime.h>
#include <math.h>

#define Bb 1024
#define Lh 320
#define Dh 128
#define Eh 8
#define Kh 2
#define Ph 96
#define LK 32

#define FMA2(a,b,c) asm("fma.rn.f32x2 %0,%1,%2,%0;" : "+l"(a) : "l"(b), "l"(c))

// ---------------- scratch (device globals; no allocs allowed) ----------------
__device__ float g_buf[Bb * Lh];        // (B, L)
__device__ float gate_val[Bb * Kh];     // top-2 gate weights per row
__device__ int   gate_idx[Bb * Kh];     // top-2 expert ids per row
__device__ float imp_buf[Eh];           // importance = gates.sum(0)
__device__ float load_buf[Eh];          // load = prob.sum(0)

// ---------------- kernel 0: zero the accumulators -----------------------------
__global__ void zero_kernel() {
    int t = threadIdx.x;
    if (t < Eh) { imp_buf[t] = 0.f; load_buf[t] = 0.f; }
}

// ---------------- kernel 1: g[b,l] = x[b,l,:]·start_w + start_b ---------------
__global__ void g_kernel(const float* __restrict__ x,
                         const float* __restrict__ start_w,
                         const float* __restrict__ start_b) {
    int warp = (blockIdx.x * blockDim.x + threadIdx.x) >> 5;
    int lane = threadIdx.x & 31;
    if (warp >= Bb * Lh) return;
    float4 xv = ((const float4*)(x + (size_t)warp * Dh))[lane];
    float4 wv = ((const float4*)start_w)[lane];
    float s = xv.x * wv.x + xv.y * wv.y + xv.z * wv.z + xv.w * wv.w;
#pragma unroll
    for (int o = 16; o; o >>= 1) s += __shfl_xor_sync(0xffffffffu, s, o);
    if (lane == 0) g_buf[warp] = s + start_b[0];
}

// ---------------- kernel 2: gating per batch row -------------------------------
__device__ __forceinline__ float cdf_f(float v) {
    return 0.5f * (1.f + erff(v * 0.7071067811865475f));
}

__global__ void gate_kernel(const float* __restrict__ w_gate,
                            const float* __restrict__ w_noise,
                            const float* __restrict__ noise) {
    int b = blockIdx.x;
    int wid = threadIdx.x >> 5, lane = threadIdx.x & 31;
    __shared__ float sc[Eh], sn[Eh];
    const float* grow = g_buf + (size_t)b * Lh;
    float c = 0.f, nn = 0.f;
    for (int l = lane; l < Lh; l += 32) {
        float gv = grow[l];
        c  += gv * w_gate [l * Eh + wid];
        nn += gv * w_noise[l * Eh + wid];
    }
#pragma unroll
    for (int o = 16; o; o >>= 1) {
        c  += __shfl_xor_sync(0xffffffffu, c,  o);
        nn += __shfl_xor_sync(0xffffffffu, nn, o);
    }
    if (lane == 0) { sc[wid] = c; sn[wid] = nn; }
    __syncthreads();
    if (threadIdx.x == 0) {
        float clean[Eh], std_[Eh], noisy[Eh];
#pragma unroll
        for (int e = 0; e < Eh; e++) {
            clean[e] = sc[e];
            float v = sn[e];
            float sp = fmaxf(v, 0.f) + log1pf(expf(-fabsf(v)));
            std_[e] = sp + 0.01f;
            noisy[e] = clean[e] + noise[b * Eh + e] * std_[e];
        }
        int   idx[3];
        float val[3];
        bool used[Eh];
#pragma unroll
        for (int e = 0; e < Eh; e++) used[e] = false;
        for (int k = 0; k < 3; k++) {
            int bi = -1; float bv = -3.4e38f;
            for (int e = 0; e < Eh; e++)
                if (!used[e] && noisy[e] > bv) { bv = noisy[e]; bi = e; }
            used[bi] = true; idx[k] = bi; val[k] = bv;
        }
        float e1 = expf(val[1] - val[0]);
        float den = 1.f + e1;
        float g0 = 1.f / den, g1 = e1 / den;
        gate_val[b * 2]     = g0;  gate_val[b * 2 + 1] = g1;
        gate_idx[b * 2]     = idx[0]; gate_idx[b * 2 + 1] = idx[1];
        atomicAdd(&imp_buf[idx[0]], g0);
        atomicAdd(&imp_buf[idx[1]], g1);
        float thr_in = val[2], thr_out = val[1];
#pragma unroll
        for (int e = 0; e < Eh; e++) {
            float cc = isnan(clean[e]) ? 0.f : clean[e];
            float t  = (noisy[e] > thr_in) ? thr_in : thr_out;
            float prob = cdf_f((cc - t) / std_[e]);
            atomicAdd(&load_buf[e], prob);
        }
    }
}

// ---------------- kernel 3: balance loss ---------------------------------------
__global__ void balance_kernel(float* __restrict__ out, int off) {
    if (threadIdx.x == 0) {
        float mi = 0.f, ml = 0.f;
        for (int e = 0; e < Eh; e++) { mi += imp_buf[e]; ml += load_buf[e]; }
        mi /= Eh; ml /= Eh;
        float vi = 0.f, vl = 0.f;
        for (int e = 0; e < Eh; e++) {
            float a = imp_buf[e] - mi;  vi += a * a;
            float c = load_buf[e] - ml; vl += c * c;
        }
        vi /= (Eh - 1); vl /= (Eh - 1);
        out[off]     = 0.01f * (vi / (mi * mi + 1e-10f) + vl / (ml * ml + 1e-10f));
        out[off + 1] = 0.f;
    }
}

// ---------------- kernel 4: main batched GEMM ----------------------------------
// One CTA per b. out[b] (96p x 128d) = W_b^T @ x[b] + gate-weighted bias.
// 192 threads = 6 warps. Warp owns a 16-wide p block; lanes span d (4 d each).
// Weights are staged in smem PRE-DUPLICATED ({w,w} pairs) so that a single
// broadcast LDS.128 yields two f32x2-ready operands — no mov.b64 packing in
// the inner loop. All w loads are warp-uniform (broadcast, conflict-free).
__global__ __launch_bounds__(192, 3) void moe_gemm_kernel(
    const float* __restrict__ x,
    const float* __restrict__ expert_w,
    const float* __restrict__ expert_b,
    float* __restrict__ out)
{
    __shared__ float xs[LK * Dh];        // 16 KB
    __shared__ float wsd[LK * Ph * 2];   // 24 KB, duplicated pairs
    int b    = blockIdx.x;
    int tid  = threadIdx.x;
    int lane = tid & 31;
    int wid  = tid >> 5;

    float g0 = gate_val[b * 2],  g1 = gate_val[b * 2 + 1];
    int   e0 = gate_idx[b * 2],  e1 = gate_idx[b * 2 + 1];

    const float* xg = x + (size_t)b * Lh * Dh;
    const float* w0 = expert_w + (size_t)e0 * Lh * Ph;
    const float* w1 = expert_w + (size_t)e1 * Lh * Ph;

    unsigned long long acc[16][2];
#pragma unroll
    for (int i = 0; i < 16; i++) { acc[i][0] = 0ull; acc[i][1] = 0ull; }

    int wp = tid % Ph;     // p column this thread combines (0..95)
    int wl = tid / Ph;     // 0 or 1

    for (int kc = 0; kc < Lh / LK; kc++) {
        // stage x chunk (32x128) as float4 (1024 vecs / 192 threads)
        const float4* xg4 = (const float4*)(xg + kc * LK * Dh);
        float4* xs4 = (float4*)xs;
        for (int i = tid; i < LK * Dh / 4; i += 192) xs4[i] = xg4[i];
        // stage combined, duplicated weight chunk (32 x 96 -> 32 x 192)
#pragma unroll
        for (int k = 0; k < 16; k++) {
            int l = wl + 2 * k;
            int gi = (kc * LK + l) * Ph + wp;
            float v = g0 * w0[gi] + g1 * w1[gi];
            *(float2*)&wsd[l * (2 * Ph) + 2 * wp] = make_float2(v, v);
        }
        __syncthreads();

#pragma unroll 4
        for (int lk = 0; lk < LK; lk++) {
            ulonglong2 xv = *(const ulonglong2*)&xs[lk * Dh + lane * 4];
            const float* wrow = &wsd[lk * (2 * Ph) + wid * 32];
#pragma unroll
            for (int half = 0; half < 2; half++) {
                ulonglong2 wv0 = *(const ulonglong2*)(wrow + half * 16);
                ulonglong2 wv1 = *(const ulonglong2*)(wrow + half * 16 + 4);
                ulonglong2 wv2 = *(const ulonglong2*)(wrow + half * 16 + 8);
                ulonglong2 wv3 = *(const ulonglong2*)(wrow + half * 16 + 12);
                int pb = half * 8;
                FMA2(acc[pb + 0][0], wv0.x, xv.x); FMA2(acc[pb + 0][1], wv0.x, xv.y);
                FMA2(acc[pb + 1][0], wv0.y, xv.x); FMA2(acc[pb + 1][1], wv0.y, xv.y);
                FMA2(acc[pb + 2][0], wv1.x, xv.x); FMA2(acc[pb + 2][1], wv1.x, xv.y);
                FMA2(acc[pb + 3][0], wv1.y, xv.x); FMA2(acc[pb + 3][1], wv1.y, xv.y);
                FMA2(acc[pb + 4][0], wv2.x, xv.x); FMA2(acc[pb + 4][1], wv2.x, xv.y);
                FMA2(acc[pb + 5][0], wv2.y, xv.x); FMA2(acc[pb + 5][1], wv2.y, xv.y);
                FMA2(acc[pb + 6][0], wv3.x, xv.x); FMA2(acc[pb + 6][1], wv3.x, xv.y);
                FMA2(acc[pb + 7][0], wv3.y, xv.x); FMA2(acc[pb + 7][1], wv3.y, xv.y);
            }
        }
        __syncthreads();
    }

    // epilogue: + g0*expert_b[e0] + g1*expert_b[e1]
    const float* b0 = expert_b + (size_t)e0 * Ph * Dh;
    const float* b1 = expert_b + (size_t)e1 * Ph * Dh;
    float* ob = out + (size_t)b * Ph * Dh;
    int d = lane * 4;
#pragma unroll
    for (int pl = 0; pl < 16; pl++) {
        int p = wid * 16 + pl;
        int off = p * Dh + d;
        float r0, r1, r2, r3;
        asm("mov.b64 {%0,%1},%2;" : "=f"(r0), "=f"(r1) : "l"(acc[pl][0]));
        asm("mov.b64 {%0,%1},%2;" : "=f"(r2), "=f"(r3) : "l"(acc[pl][1]));
        float4 bb0 = *(const float4*)&b0[off];
        float4 bb1 = *(const float4*)&b1[off];
        float4 o;
        o.x = r0 + g0 * bb0.x + g1 * bb1.x;
        o.y = r1 + g0 * bb0.y + g1 * bb1.y;
        o.z = r2 + g0 * bb0.z + g1 * bb1.z;
        o.w = r3 + g0 * bb0.w + g1 * bb1.w;
        *(float4*)&ob[off] = o;
    }
}

// ---------------- launch ---------------------------------------------------------
extern "C" void kernel_launch(void* const* d_in, const int* in_sizes, int n_in,
                              void* d_out, int out_size) {
    const float* x        = (const float*)d_in[0];
    const float* noise    = (const float*)d_in[2];
    const float* start_w  = (const float*)d_in[3];
    const float* start_b  = (const float*)d_in[4];
    const float* w_gate   = (const float*)d_in[5];
    const float* w_noise  = (const float*)d_in[6];
    const float* expert_w = (const float*)d_in[7];
    const float* expert_b = (const float*)d_in[8];
    if (in_sizes[7] == Eh * Ph * Dh && in_sizes[8] == Eh * Lh * Ph) {
        expert_b = (const float*)d_in[7];
        expert_w = (const float*)d_in[8];
    }
    float* out = (float*)d_out;

    zero_kernel<<<1, 32>>>();
    g_kernel<<<(Bb * Lh) / 8, 256>>>(x, start_w, start_b);
    gate_kernel<<<Bb, 256>>>(w_gate, w_noise, noise);
    balance_kernel<<<1, 32>>>(out, out_size - 2);
    moe_gemm_kernel<<<Bb, 192>>>(x, expert_w, expert_b, out);
}

// round 4
// speedup vs baseline: 2.6301x; 2.1159x over previous
#include <cuda_runtime.h>
#include <cuda_bf16.h>
#include <math.h>
#include <stdint.h>

#define Bb 1024
#define Lh 320
#define Dh 128
#define Eh 8
#define Ph 96
#define LKC 64           // l-chunk per stage

// ======================= PTX helpers =======================
__device__ __forceinline__ uint32_t smem_u32(const void* p) {
    uint32_t a;
    asm("{ .reg .u64 t; cvta.to.shared.u64 t, %1; cvt.u32.u64 %0, t; }" : "=r"(a) : "l"(p));
    return a;
}
#define LDSM_X4(r, addr) \
    asm volatile("ldmatrix.sync.aligned.m8n8.x4.shared.b16 {%0,%1,%2,%3}, [%4];" \
        : "=r"((r)[0]), "=r"((r)[1]), "=r"((r)[2]), "=r"((r)[3]) : "r"(addr))
#define LDSM_X4_T(r, addr) \
    asm volatile("ldmatrix.sync.aligned.m8n8.x4.trans.shared.b16 {%0,%1,%2,%3}, [%4];" \
        : "=r"((r)[0]), "=r"((r)[1]), "=r"((r)[2]), "=r"((r)[3]) : "r"(addr))
#define MMA16816(c, a, b0, b1) \
    asm volatile("mma.sync.aligned.m16n8k16.row.col.f32.bf16.bf16.f32 " \
        "{%0,%1,%2,%3}, {%4,%5,%6,%7}, {%8,%9}, {%0,%1,%2,%3};" \
        : "+f"((c)[0]), "+f"((c)[1]), "+f"((c)[2]), "+f"((c)[3]) \
        : "r"((a)[0]), "r"((a)[1]), "r"((a)[2]), "r"((a)[3]), "r"(b0), "r"(b1))

// ======================= scratch =======================
__device__ float g_buf[Bb * Lh];
__device__ float gate_val[Bb * 2];
__device__ int   gate_idx[Bb * 2];
__device__ float imp_buf[Eh];
__device__ float load_buf[Eh];
// pre-transposed expert weights, fp32: Wt[e][p=96][l=320]
__device__ float Wt[Eh * Ph * Lh];

// ======================= small kernels =======================
__global__ void zero_kernel() {
    int t = threadIdx.x;
    if (t < Eh) { imp_buf[t] = 0.f; load_buf[t] = 0.f; }
}

__global__ void prep_w_kernel(const float* __restrict__ expert_w) {
    int gid = blockIdx.x * blockDim.x + threadIdx.x;
    if (gid >= Eh * Ph * Lh) return;
    int e = gid / (Ph * Lh);
    int r = gid % (Ph * Lh);
    int p = r / Lh;
    int l = r % Lh;
    Wt[gid] = expert_w[((size_t)e * Lh + l) * Ph + p];
}

__global__ void g_kernel(const float* __restrict__ x,
                         const float* __restrict__ start_w,
                         const float* __restrict__ start_b) {
    int warp = (blockIdx.x * blockDim.x + threadIdx.x) >> 5;
    int lane = threadIdx.x & 31;
    if (warp >= Bb * Lh) return;
    float4 xv = ((const float4*)(x + (size_t)warp * Dh))[lane];
    float4 wv = ((const float4*)start_w)[lane];
    float s = xv.x * wv.x + xv.y * wv.y + xv.z * wv.z + xv.w * wv.w;
#pragma unroll
    for (int o = 16; o; o >>= 1) s += __shfl_xor_sync(0xffffffffu, s, o);
    if (lane == 0) g_buf[warp] = s + start_b[0];
}

__device__ __forceinline__ float cdf_f(float v) {
    return 0.5f * (1.f + erff(v * 0.7071067811865475f));
}

__global__ void gate_kernel(const float* __restrict__ w_gate,
                            const float* __restrict__ w_noise,
                            const float* __restrict__ noise) {
    int b = blockIdx.x;
    int wid = threadIdx.x >> 5, lane = threadIdx.x & 31;
    __shared__ float sc[Eh], sn[Eh];
    const float* grow = g_buf + (size_t)b * Lh;
    float c = 0.f, nn = 0.f;
    for (int l = lane; l < Lh; l += 32) {
        float gv = grow[l];
        c  += gv * w_gate [l * Eh + wid];
        nn += gv * w_noise[l * Eh + wid];
    }
#pragma unroll
    for (int o = 16; o; o >>= 1) {
        c  += __shfl_xor_sync(0xffffffffu, c,  o);
        nn += __shfl_xor_sync(0xffffffffu, nn, o);
    }
    if (lane == 0) { sc[wid] = c; sn[wid] = nn; }
    __syncthreads();
    if (threadIdx.x == 0) {
        float clean[Eh], std_[Eh], noisy[Eh];
#pragma unroll
        for (int e = 0; e < Eh; e++) {
            clean[e] = sc[e];
            float v = sn[e];
            float sp = fmaxf(v, 0.f) + log1pf(expf(-fabsf(v)));
            std_[e] = sp + 0.01f;
            noisy[e] = clean[e] + noise[b * Eh + e] * std_[e];
        }
        int idx[3]; float val[3]; bool used[Eh];
#pragma unroll
        for (int e = 0; e < Eh; e++) used[e] = false;
        for (int k = 0; k < 3; k++) {
            int bi = -1; float bv = -3.4e38f;
            for (int e = 0; e < Eh; e++)
                if (!used[e] && noisy[e] > bv) { bv = noisy[e]; bi = e; }
            used[bi] = true; idx[k] = bi; val[k] = bv;
        }
        float e1 = expf(val[1] - val[0]);
        float den = 1.f + e1;
        float g0 = 1.f / den, g1 = e1 / den;
        gate_val[b * 2] = g0;  gate_val[b * 2 + 1] = g1;
        gate_idx[b * 2] = idx[0]; gate_idx[b * 2 + 1] = idx[1];
        atomicAdd(&imp_buf[idx[0]], g0);
        atomicAdd(&imp_buf[idx[1]], g1);
        float thr_in = val[2], thr_out = val[1];
#pragma unroll
        for (int e = 0; e < Eh; e++) {
            float cc = isnan(clean[e]) ? 0.f : clean[e];
            float t  = (noisy[e] > thr_in) ? thr_in : thr_out;
            atomicAdd(&load_buf[e], cdf_f((cc - t) / std_[e]));
        }
    }
}

__global__ void balance_kernel(float* __restrict__ out, int off) {
    if (threadIdx.x == 0) {
        float mi = 0.f, ml = 0.f;
        for (int e = 0; e < Eh; e++) { mi += imp_buf[e]; ml += load_buf[e]; }
        mi /= Eh; ml /= Eh;
        float vi = 0.f, vl = 0.f;
        for (int e = 0; e < Eh; e++) {
            float a = imp_buf[e] - mi;  vi += a * a;
            float c = load_buf[e] - ml; vl += c * c;
        }
        vi /= (Eh - 1); vl /= (Eh - 1);
        out[off]     = 0.01f * (vi / (mi * mi + 1e-10f) + vl / (ml * ml + 1e-10f));
        out[off + 1] = 0.f;
    }
}

// ======================= HMMA GEMM =======================
// One CTA per b (256 thr, 8 warps in 2x4). C[96p x 128d] = W_b^T @ x[b].
// A = combined gate-weighted weights, bf16 hi/lo; B = x, bf16 hi/lo.
// 3 MMA chains (hi*hi, hi*lo, lo*hi) into one fp32 accumulator set.
// smem layout (dynamic, 57344 B):
//   Ahi [96][64] bf16 @ 0       (12288)
//   Alo              @ 12288    (12288)
//   Bhi [64][128] bf16 @ 24576  (16384)
//   Blo              @ 40960    (16384)
#define SM_AHI 0
#define SM_ALO 12288
#define SM_BHI 24576
#define SM_BLO 40960
#define SMEM_TOTAL 57344

__global__ void __launch_bounds__(256, 2) moe_hmma_kernel(
    const float* __restrict__ x,
    const float* __restrict__ expert_b,
    float* __restrict__ out)
{
    extern __shared__ char smem[];
    const uint32_t sbase = smem_u32(smem);
    const int b    = blockIdx.x;
    const int tid  = threadIdx.x;
    const int wid  = tid >> 5;
    const int lane = tid & 31;
    const int wm   = wid >> 2;      // 0..1
    const int wn   = wid & 3;       // 0..3

    const float g0 = gate_val[b * 2], g1 = gate_val[b * 2 + 1];
    const int   e0 = gate_idx[b * 2], e1 = gate_idx[b * 2 + 1];

    const float4* xg4 = (const float4*)(x + (size_t)b * Lh * Dh);
    const float4* w0g = (const float4*)(Wt + (size_t)e0 * Ph * Lh);
    const float4* w1g = (const float4*)(Wt + (size_t)e1 * Ph * Lh);

    float acc[3][4][4];
#pragma unroll
    for (int i = 0; i < 3; i++)
#pragma unroll
        for (int j = 0; j < 4; j++)
#pragma unroll
            for (int q = 0; q < 4; q++) acc[i][j][q] = 0.f;

    const int arow = lane & 15, acolh = lane >> 4;   // ldmatrix lane mapping

    for (int kc = 0; kc < Lh / LKC; kc++) {
        // ---- stage A: combine + split, 96x64 (1536 float4 work items) ----
#pragma unroll
        for (int it = 0; it < 6; it++) {
            int i  = tid + it * 256;       // 0..1535
            int p  = i >> 4;
            int lq = i & 15;
            int l  = lq * 4;
            float4 a0 = w0g[(p * Lh + kc * LKC + l) >> 2];
            float4 a1 = w1g[(p * Lh + kc * LKC + l) >> 2];
            float4 v;
            v.x = g0 * a0.x + g1 * a1.x;
            v.y = g0 * a0.y + g1 * a1.y;
            v.z = g0 * a0.z + g1 * a1.z;
            v.w = g0 * a0.w + g1 * a1.w;
            uint32_t h0, h1, q0, q1;
            asm("cvt.rn.bf16x2.f32 %0, %1, %2;" : "=r"(h0) : "f"(v.y), "f"(v.x));
            asm("cvt.rn.bf16x2.f32 %0, %1, %2;" : "=r"(h1) : "f"(v.w), "f"(v.z));
            float r0 = v.x - __uint_as_float(h0 << 16);
            float r1 = v.y - __uint_as_float(h0 & 0xffff0000u);
            float r2 = v.z - __uint_as_float(h1 << 16);
            float r3 = v.w - __uint_as_float(h1 & 0xffff0000u);
            asm("cvt.rn.bf16x2.f32 %0, %1, %2;" : "=r"(q0) : "f"(r1), "f"(r0));
            asm("cvt.rn.bf16x2.f32 %0, %1, %2;" : "=r"(q1) : "f"(r3), "f"(r2));
            uint32_t off = (uint32_t)(p * 128 + ((((l >> 3)) ^ (p & 7)) << 4) + (l & 7) * 2);
            *(uint2*)(smem + SM_AHI + off) = make_uint2(h0, h1);
            *(uint2*)(smem + SM_ALO + off) = make_uint2(q0, q1);
        }
        // ---- stage B: x chunk 64x128 split (2048 float4 work items) ----
#pragma unroll
        for (int it = 0; it < 8; it++) {
            int i  = tid + it * 256;       // 0..2047
            int l  = i >> 5;
            int dq = i & 31;
            int d  = dq * 4;
            float4 xv = xg4[(size_t)(kc * LKC + l) * 32 + dq];
            uint32_t h0, h1, q0, q1;
            asm("cvt.rn.bf16x2.f32 %0, %1, %2;" : "=r"(h0) : "f"(xv.y), "f"(xv.x));
            asm("cvt.rn.bf16x2.f32 %0, %1, %2;" : "=r"(h1) : "f"(xv.w), "f"(xv.z));
            float r0 = xv.x - __uint_as_float(h0 << 16);
            float r1 = xv.y - __uint_as_float(h0 & 0xffff0000u);
            float r2 = xv.z - __uint_as_float(h1 << 16);
            float r3 = xv.w - __uint_as_float(h1 & 0xffff0000u);
            asm("cvt.rn.bf16x2.f32 %0, %1, %2;" : "=r"(q0) : "f"(r1), "f"(r0));
            asm("cvt.rn.bf16x2.f32 %0, %1, %2;" : "=r"(q1) : "f"(r3), "f"(r2));
            uint32_t off = (uint32_t)(l * 256 + ((((d >> 3)) ^ (l & 7)) << 4) + (d & 7) * 2);
            *(uint2*)(smem + SM_BHI + off) = make_uint2(h0, h1);
            *(uint2*)(smem + SM_BLO + off) = make_uint2(q0, q1);
        }
        __syncthreads();

        // ---- MMA: 4 k16-steps per chunk ----
#pragma unroll
        for (int ks = 0; ks < 4; ks++) {
            int k0 = ks * 16;
            uint32_t ahi[3][4], alo[3][4];
#pragma unroll
            for (int fm = 0; fm < 3; fm++) {
                int m = wm * 48 + fm * 16 + arow;
                uint32_t aoff = (uint32_t)(m * 128 + ((((k0 >> 3) + acolh) ^ (m & 7)) << 4));
                LDSM_X4(ahi[fm], sbase + SM_AHI + aoff);
                LDSM_X4(alo[fm], sbase + SM_ALO + aoff);
            }
            uint32_t bhi[2][4], blo[2][4];
#pragma unroll
            for (int fp = 0; fp < 2; fp++) {
                int n0 = wn * 32 + fp * 16;
                int k  = k0 + arow;
                uint32_t boff = (uint32_t)(k * 256 + ((((n0 >> 3) + acolh) ^ (k & 7)) << 4));
                LDSM_X4_T(bhi[fp], sbase + SM_BHI + boff);
                LDSM_X4_T(blo[fp], sbase + SM_BLO + boff);
            }
#pragma unroll
            for (int fm = 0; fm < 3; fm++)
#pragma unroll
                for (int fp = 0; fp < 2; fp++)
#pragma unroll
                    for (int sub = 0; sub < 2; sub++) {
                        int fn = fp * 2 + sub;
                        MMA16816(acc[fm][fn], ahi[fm], bhi[fp][sub * 2], bhi[fp][sub * 2 + 1]);
                        MMA16816(acc[fm][fn], ahi[fm], blo[fp][sub * 2], blo[fp][sub * 2 + 1]);
                        MMA16816(acc[fm][fn], alo[fm], bhi[fp][sub * 2], bhi[fp][sub * 2 + 1]);
                    }
        }
        __syncthreads();
    }

    // ---- epilogue: add gate-weighted bias, store from fragments ----
    const float* b0e = expert_b + (size_t)e0 * Ph * Dh;
    const float* b1e = expert_b + (size_t)e1 * Ph * Dh;
    float* ob = out + (size_t)b * Ph * Dh;
    int pr = lane >> 2, dc = (lane & 3) * 2;
#pragma unroll
    for (int fm = 0; fm < 3; fm++) {
#pragma unroll
        for (int fn = 0; fn < 4; fn++) {
            int p = wm * 48 + fm * 16 + pr;
            int d = wn * 32 + fn * 8 + dc;
#pragma unroll
            for (int half = 0; half < 2; half++) {
                int pp = p + half * 8;
                int off = pp * Dh + d;
                float2 v0 = *(const float2*)&b0e[off];
                float2 v1 = *(const float2*)&b1e[off];
                float2 o;
                o.x = acc[fm][fn][half * 2 + 0] + g0 * v0.x + g1 * v1.x;
                o.y = acc[fm][fn][half * 2 + 1] + g0 * v0.y + g1 * v1.y;
                *(float2*)&ob[off] = o;
            }
        }
    }
}

// ======================= launch =======================
extern "C" void kernel_launch(void* const* d_in, const int* in_sizes, int n_in,
                              void* d_out, int out_size) {
    const float* x        = (const float*)d_in[0];
    const float* noise    = (const float*)d_in[2];
    const float* start_w  = (const float*)d_in[3];
    const float* start_b  = (const float*)d_in[4];
    const float* w_gate   = (const float*)d_in[5];
    const float* w_noise  = (const float*)d_in[6];
    const float* expert_w = (const float*)d_in[7];
    const float* expert_b = (const float*)d_in[8];
    if (in_sizes[7] == Eh * Ph * Dh && in_sizes[8] == Eh * Lh * Ph) {
        expert_b = (const float*)d_in[7];
        expert_w = (const float*)d_in[8];
    }
    float* out = (float*)d_out;

    cudaFuncSetAttribute(moe_hmma_kernel,
                         cudaFuncAttributeMaxDynamicSharedMemorySize, SMEM_TOTAL);

    zero_kernel<<<1, 32>>>();
    prep_w_kernel<<<(Eh * Ph * Lh + 255) / 256, 256>>>(expert_w);
    g_kernel<<<(Bb * Lh) / 8, 256>>>(x, start_w, start_b);
    gate_kernel<<<Bb, 256>>>(w_gate, w_noise, noise);
    balance_kernel<<<1, 32>>>(out, out_size - 2);
    moe_hmma_kernel<<<Bb, 256, SMEM_TOTAL>>>(x, expert_b, out);
}

// round 5
// speedup vs baseline: 3.1115x; 1.1830x over previous
#include <cuda_runtime.h>
#include <cuda_bf16.h>
#include <math.h>
#include <stdint.h>

#define Bb 1024
#define Lh 320
#define Dh 128
#define Eh 8
#define Ph 96
#define LKC 64           // l-chunk per stage

// ======================= PTX helpers =======================
__device__ __forceinline__ uint32_t smem_u32(const void* p) {
    uint32_t a;
    asm("{ .reg .u64 t; cvta.to.shared.u64 t, %1; cvt.u32.u64 %0, t; }" : "=r"(a) : "l"(p));
    return a;
}
#define LDSM_X4(r, addr) \
    asm volatile("ldmatrix.sync.aligned.m8n8.x4.shared.b16 {%0,%1,%2,%3}, [%4];" \
        : "=r"((r)[0]), "=r"((r)[1]), "=r"((r)[2]), "=r"((r)[3]) : "r"(addr))
#define LDSM_X4_T(r, addr) \
    asm volatile("ldmatrix.sync.aligned.m8n8.x4.trans.shared.b16 {%0,%1,%2,%3}, [%4];" \
        : "=r"((r)[0]), "=r"((r)[1]), "=r"((r)[2]), "=r"((r)[3]) : "r"(addr))
#define MMA16816(c, a, b0, b1) \
    asm volatile("mma.sync.aligned.m16n8k16.row.col.f32.bf16.bf16.f32 " \
        "{%0,%1,%2,%3}, {%4,%5,%6,%7}, {%8,%9}, {%0,%1,%2,%3};" \
        : "+f"((c)[0]), "+f"((c)[1]), "+f"((c)[2]), "+f"((c)[3]) \
        : "r"((a)[0]), "r"((a)[1]), "r"((a)[2]), "r"((a)[3]), "r"(b0), "r"(b1))

// truncation-based hi/lo split of 2 floats -> 2 packed bf16x2
__device__ __forceinline__ void split2(float a0, float a1, uint32_t& hip, uint32_t& lop) {
    uint32_t b0 = __float_as_uint(a0), b1 = __float_as_uint(a1);
    uint32_t h;
    asm("prmt.b32 %0, %1, %2, 0x7632;" : "=r"(h) : "r"(b0), "r"(b1));
    float h0 = __uint_as_float(b0 & 0xffff0000u);
    float h1 = __uint_as_float(b1 & 0xffff0000u);
    float l0 = a0 - h0, l1 = a1 - h1;
    uint32_t lo;
    asm("cvt.rn.bf16x2.f32 %0, %1, %2;" : "=r"(lo) : "f"(l1), "f"(l0));
    hip = h; lop = lo;
}

// ======================= scratch =======================
__device__ float imp_buf[Eh];
__device__ float load_buf[Eh];
// pre-transposed expert weights, fp32: Wt[e][p=96][l=320]
__device__ float Wt[Eh * Ph * Lh];

// ======================= small kernels =======================
__global__ void zero_kernel() {
    int t = threadIdx.x;
    if (t < Eh) { imp_buf[t] = 0.f; load_buf[t] = 0.f; }
}

__global__ void prep_w_kernel(const float* __restrict__ expert_w) {
    int gid = blockIdx.x * blockDim.x + threadIdx.x;
    if (gid >= Eh * Ph * Lh) return;
    int e = gid / (Ph * Lh);
    int r = gid % (Ph * Lh);
    int p = r / Lh;
    int l = r % Lh;
    Wt[gid] = expert_w[((size_t)e * Lh + l) * Ph + p];
}

__global__ void balance_kernel(float* __restrict__ out, int off) {
    if (threadIdx.x == 0) {
        float mi = 0.f, ml = 0.f;
        for (int e = 0; e < Eh; e++) { mi += imp_buf[e]; ml += load_buf[e]; }
        mi /= Eh; ml /= Eh;
        float vi = 0.f, vl = 0.f;
        for (int e = 0; e < Eh; e++) {
            float a = imp_buf[e] - mi;  vi += a * a;
            float c = load_buf[e] - ml; vl += c * c;
        }
        vi /= (Eh - 1); vl /= (Eh - 1);
        out[off]     = 0.01f * (vi / (mi * mi + 1e-10f) + vl / (ml * ml + 1e-10f));
        out[off + 1] = 0.f;
    }
}

__device__ __forceinline__ float cdf_f(float v) {
    return 0.5f * (1.f + erff(v * 0.7071067811865475f));
}

// ======================= fused gating + HMMA GEMM =======================
// One CTA per b (256 thr, 8 warps in 2x4).
// Phase 1 (gating): g[l] = x[b,l,:]·start_w + start_b; clean/noisy logits per
//   expert; top-3; softmax over top-2; load/importance atomics.
// Phase 2 (GEMM): C[96p x 128d] = (g0*W[e0]+g1*W[e1])^T @ x[b], bf16 hi/lo
//   split, 3 HMMA chains, fp32 accum; bias epilogue.
// smem (dynamic, 57344 B): Ahi@0(12288) Alo@12288 Bhi@24576(16384) Blo@40960
// Gating scratch overlays the A region (consumed before first staging store).
#define SM_AHI 0
#define SM_ALO 12288
#define SM_BHI 24576
#define SM_BLO 40960
#define SMEM_TOTAL 57344

__global__ void __launch_bounds__(256, 2) moe_fused_kernel(
    const float* __restrict__ x,
    const float* __restrict__ expert_b,
    const float* __restrict__ start_w,
    const float* __restrict__ start_b,
    const float* __restrict__ w_gate,
    const float* __restrict__ w_noise,
    const float* __restrict__ noise,
    float* __restrict__ out)
{
    extern __shared__ char smem[];
    const uint32_t sbase = smem_u32(smem);
    const int b    = blockIdx.x;
    const int tid  = threadIdx.x;
    const int wid  = tid >> 5;
    const int lane = tid & 31;
    const int wm   = wid >> 2;      // 0..1
    const int wn   = wid & 3;       // 0..3

    float* gr   = (float*)smem;            // [320]
    float* sc   = (float*)(smem + 1280);   // [8]
    float* sn   = (float*)(smem + 1312);   // [8]
    float* ginf = (float*)(smem + 1344);   // g0,g1,e0,e1

    const float4* xg4 = (const float4*)(x + (size_t)b * Lh * Dh);

    // ---- phase 1a: g row (8 warps x 40 rows) ----
    {
        float4 wv = ((const float4*)start_w)[lane];
        float sb = start_b[0];
        for (int l = wid * 40; l < wid * 40 + 40; l++) {
            float4 xv = xg4[l * 32 + lane];
            float s = xv.x * wv.x + xv.y * wv.y + xv.z * wv.z + xv.w * wv.w;
#pragma unroll
            for (int o = 16; o; o >>= 1) s += __shfl_xor_sync(0xffffffffu, s, o);
            if (lane == 0) gr[l] = s + sb;
        }
    }
    __syncthreads();
    // ---- phase 1b: clean/noise logits (warp e -> expert e) ----
    {
        float c = 0.f, nn = 0.f;
        for (int l = lane; l < Lh; l += 32) {
            float gv = gr[l];
            c  += gv * w_gate [l * Eh + wid];
            nn += gv * w_noise[l * Eh + wid];
        }
#pragma unroll
        for (int o = 16; o; o >>= 1) {
            c  += __shfl_xor_sync(0xffffffffu, c,  o);
            nn += __shfl_xor_sync(0xffffffffu, nn, o);
        }
        if (lane == 0) { sc[wid] = c; sn[wid] = nn; }
    }
    __syncthreads();
    // ---- phase 1c: top-k, gates, atomics (thread 0) ----
    if (tid == 0) {
        float clean[Eh], std_[Eh], noisy[Eh];
#pragma unroll
        for (int e = 0; e < Eh; e++) {
            clean[e] = sc[e];
            float v = sn[e];
            float sp = fmaxf(v, 0.f) + log1pf(expf(-fabsf(v)));
            std_[e] = sp + 0.01f;
            noisy[e] = clean[e] + noise[b * Eh + e] * std_[e];
        }
        int idx[3]; float val[3]; bool used[Eh];
#pragma unroll
        for (int e = 0; e < Eh; e++) used[e] = false;
        for (int k = 0; k < 3; k++) {
            int bi = -1; float bv = -3.4e38f;
            for (int e = 0; e < Eh; e++)
                if (!used[e] && noisy[e] > bv) { bv = noisy[e]; bi = e; }
            used[bi] = true; idx[k] = bi; val[k] = bv;
        }
        float e1v = expf(val[1] - val[0]);
        float den = 1.f + e1v;
        float g0 = 1.f / den, g1 = e1v / den;
        ginf[0] = g0; ginf[1] = g1;
        ((int*)ginf)[2] = idx[0]; ((int*)ginf)[3] = idx[1];
        atomicAdd(&imp_buf[idx[0]], g0);
        atomicAdd(&imp_buf[idx[1]], g1);
        float thr_in = val[2], thr_out = val[1];
#pragma unroll
        for (int e = 0; e < Eh; e++) {
            float cc = isnan(clean[e]) ? 0.f : clean[e];
            float t  = (noisy[e] > thr_in) ? thr_in : thr_out;
            atomicAdd(&load_buf[e], cdf_f((cc - t) / std_[e]));
        }
    }
    __syncthreads();
    const float g0 = ginf[0], g1 = ginf[1];
    const int   e0 = ((int*)ginf)[2], e1 = ((int*)ginf)[3];
    __syncthreads();   // everyone has gate regs before staging overwrites smem

    // ---- phase 2: GEMM ----
    const float4* w0g = (const float4*)(Wt + (size_t)e0 * Ph * Lh);
    const float4* w1g = (const float4*)(Wt + (size_t)e1 * Ph * Lh);

    float acc[3][4][4];
#pragma unroll
    for (int i = 0; i < 3; i++)
#pragma unroll
        for (int j = 0; j < 4; j++)
#pragma unroll
            for (int q = 0; q < 4; q++) acc[i][j][q] = 0.f;

    const int arow = lane & 15, acolh = lane >> 4;

    for (int kc = 0; kc < Lh / LKC; kc++) {
        // ---- stage A: combine + split, 96x64 ----
#pragma unroll
        for (int it = 0; it < 6; it++) {
            int i  = tid + it * 256;       // 0..1535
            int p  = i >> 4;
            int lq = i & 15;
            int l  = lq * 4;
            float4 a0 = w0g[(p * Lh + kc * LKC + l) >> 2];
            float4 a1 = w1g[(p * Lh + kc * LKC + l) >> 2];
            float4 v;
            v.x = g0 * a0.x + g1 * a1.x;
            v.y = g0 * a0.y + g1 * a1.y;
            v.z = g0 * a0.z + g1 * a1.z;
            v.w = g0 * a0.w + g1 * a1.w;
            uint32_t h0, h1, q0, q1;
            split2(v.x, v.y, h0, q0);
            split2(v.z, v.w, h1, q1);
            uint32_t off = (uint32_t)(p * 128 + ((((l >> 3)) ^ (p & 7)) << 4) + (l & 7) * 2);
            *(uint2*)(smem + SM_AHI + off) = make_uint2(h0, h1);
            *(uint2*)(smem + SM_ALO + off) = make_uint2(q0, q1);
        }
        // ---- stage B: x chunk 64x128 split ----
#pragma unroll
        for (int it = 0; it < 8; it++) {
            int i  = tid + it * 256;       // 0..2047
            int l  = i >> 5;
            int dq = i & 31;
            int d  = dq * 4;
            float4 xv = xg4[(size_t)(kc * LKC + l) * 32 + dq];
            uint32_t h0, h1, q0, q1;
            split2(xv.x, xv.y, h0, q0);
            split2(xv.z, xv.w, h1, q1);
            uint32_t off = (uint32_t)(l * 256 + ((((d >> 3)) ^ (l & 7)) << 4) + (d & 7) * 2);
            *(uint2*)(smem + SM_BHI + off) = make_uint2(h0, h1);
            *(uint2*)(smem + SM_BLO + off) = make_uint2(q0, q1);
        }
        __syncthreads();

        // ---- MMA: 4 k16-steps per chunk ----
#pragma unroll
        for (int ks = 0; ks < 4; ks++) {
            int k0 = ks * 16;
            uint32_t ahi[3][4], alo[3][4];
#pragma unroll
            for (int fm = 0; fm < 3; fm++) {
                int m = wm * 48 + fm * 16 + arow;
                uint32_t aoff = (uint32_t)(m * 128 + ((((k0 >> 3) + acolh) ^ (m & 7)) << 4));
                LDSM_X4(ahi[fm], sbase + SM_AHI + aoff);
                LDSM_X4(alo[fm], sbase + SM_ALO + aoff);
            }
            uint32_t bhi[2][4], blo[2][4];
#pragma unroll
            for (int fp = 0; fp < 2; fp++) {
                int n0 = wn * 32 + fp * 16;
                int k  = k0 + arow;
                uint32_t boff = (uint32_t)(k * 256 + ((((n0 >> 3) + acolh) ^ (k & 7)) << 4));
                LDSM_X4_T(bhi[fp], sbase + SM_BHI + boff);
                LDSM_X4_T(blo[fp], sbase + SM_BLO + boff);
            }
#pragma unroll
            for (int fm = 0; fm < 3; fm++)
#pragma unroll
                for (int fp = 0; fp < 2; fp++)
#pragma unroll
                    for (int sub = 0; sub < 2; sub++) {
                        int fn = fp * 2 + sub;
                        MMA16816(acc[fm][fn], ahi[fm], bhi[fp][sub * 2], bhi[fp][sub * 2 + 1]);
                        MMA16816(acc[fm][fn], ahi[fm], blo[fp][sub * 2], blo[fp][sub * 2 + 1]);
                        MMA16816(acc[fm][fn], alo[fm], bhi[fp][sub * 2], bhi[fp][sub * 2 + 1]);
                    }
        }
        __syncthreads();
    }

    // ---- epilogue: add gate-weighted bias, store ----
    const float* b0e = expert_b + (size_t)e0 * Ph * Dh;
    const float* b1e = expert_b + (size_t)e1 * Ph * Dh;
    float* ob = out + (size_t)b * Ph * Dh;
    int pr = lane >> 2, dc = (lane & 3) * 2;
#pragma unroll
    for (int fm = 0; fm < 3; fm++) {
#pragma unroll
        for (int fn = 0; fn < 4; fn++) {
            int p = wm * 48 + fm * 16 + pr;
            int d = wn * 32 + fn * 8 + dc;
#pragma unroll
            for (int half = 0; half < 2; half++) {
                int pp = p + half * 8;
                int off = pp * Dh + d;
                float2 v0 = *(const float2*)&b0e[off];
                float2 v1 = *(const float2*)&b1e[off];
                float2 o;
                o.x = acc[fm][fn][half * 2 + 0] + g0 * v0.x + g1 * v1.x;
                o.y = acc[fm][fn][half * 2 + 1] + g0 * v0.y + g1 * v1.y;
                *(float2*)&ob[off] = o;
            }
        }
    }
}

// ======================= launch =======================
extern "C" void kernel_launch(void* const* d_in, const int* in_sizes, int n_in,
                              void* d_out, int out_size) {
    const float* x        = (const float*)d_in[0];
    const float* noise    = (const float*)d_in[2];
    const float* start_w  = (const float*)d_in[3];
    const float* start_b  = (const float*)d_in[4];
    const float* w_gate   = (const float*)d_in[5];
    const float* w_noise  = (const float*)d_in[6];
    const float* expert_w = (const float*)d_in[7];
    const float* expert_b = (const float*)d_in[8];
    if (in_sizes[7] == Eh * Ph * Dh && in_sizes[8] == Eh * Lh * Ph) {
        expert_b = (const float*)d_in[7];
        expert_w = (const float*)d_in[8];
    }
    float* out = (float*)d_out;

    cudaFuncSetAttribute(moe_fused_kernel,
                         cudaFuncAttributeMaxDynamicSharedMemorySize, SMEM_TOTAL);

    zero_kernel<<<1, 32>>>();
    prep_w_kernel<<<(Eh * Ph * Lh + 255) / 256, 256>>>(expert_w);
    moe_fused_kernel<<<Bb, 256, SMEM_TOTAL>>>(x, expert_b, start_w, start_b,
                                              w_gate, w_noise, noise, out);
    balance_kernel<<<1, 32>>>(out, out_size - 2);
}